// round 16
// baseline (speedup 1.0000x reference)
#include <cuda_runtime.h>
#include <cuda_bf16.h>

// ZBL repulsion energy — R15: R14's proven pair kernel (170.7us, at the
// scattered-wavefront floor) + output zeroing folded into prep_kernel
// (removes the cudaMemsetAsync graph node; attacks the 3.9us non-pair time).
//
// Established floor: 2 random u8 gathers + 1 RED per pair = 3 divergent
// L1tex wavefronts, ~324K cyc/SM ~= 170us. All inner-loop deviations lost:
//  - R6 DSMEM cluster table: 444us (remote fabric request-rate bound)
//  - R7 smem table head:     207us (displaces L1, halves occupancy)
//  - R8 PPT=8 + batching:    209us (regs 40, occ 90->70)
//  - R9 replicated LUT:      199us (+2 ALU/lookup on non-binding conflicts)
//  - R13/R10 248us reading:  throttled-node artifact (L2/DRAM% fell, L1% rose)
// Pair kernel is byte-identical to the 174.6us R14 binary. Do not touch it.

#define KEHALF 7.199822675975274f
#define LOG2E  1.4426950408889634f
#define MAX_ATOMS 524288   // problem uses 500,000

__device__ unsigned char g_Z8[MAX_ATOMS];
__device__ float g_zlut[128];   // z-value LUT indexed by Z (0..94 used)
__device__ float g_c[12];       // b1..b4 (=sp(a_k)*sp(adiv)*log2e), c1n..c4n

__device__ __forceinline__ float ex2f(float x) {
    float y;
    asm("ex2.approx.ftz.f32 %0, %1;" : "=f"(y) : "f"(x));
    return y;
}
__device__ __forceinline__ float frcpf(float x) {
    float y;
    asm("rcp.approx.ftz.f32 %0, %1;" : "=f"(y) : "f"(x));
    return y;
}

__global__ void prep_kernel(const float* __restrict__ Zf, int natoms,
                            float* __restrict__ out, int out_n,
                            const float* adiv, const float* apow,
                            const float* c1, const float* c2,
                            const float* c3, const float* c4,
                            const float* a1, const float* a2,
                            const float* a3, const float* a4) {
    int t = blockIdx.x * blockDim.x + threadIdx.x;
    if (t < natoms && t < MAX_ATOMS)
        g_Z8[t] = (unsigned char)__float2int_rn(Zf[t]);
    if (t < out_n)
        out[t] = 0.0f;                      // replaces the memset graph node

    if (blockIdx.x == 0) {
        if (threadIdx.x < 128) {
            float spapow = log1pf(expf(*apow));
            float v = (threadIdx.x == 0) ? 0.0f
                                         : powf((float)threadIdx.x, spapow);
            g_zlut[threadIdx.x] = v;
        }
        if (threadIdx.x == 0) {
            float spadiv = log1pf(expf(*adiv));
            float sa1 = log1pf(expf(*a1));
            float sa2 = log1pf(expf(*a2));
            float sa3 = log1pf(expf(*a3));
            float sa4 = log1pf(expf(*a4));
            float c1p = log1pf(expf(*c1));
            float c2p = log1pf(expf(*c2));
            float c3p = log1pf(expf(*c3));
            float c4p = log1pf(expf(*c4));
            float inv = 1.0f / (c1p + c2p + c3p + c4p);
            g_c[0] = sa1 * spadiv * LOG2E;
            g_c[1] = sa2 * spadiv * LOG2E;
            g_c[2] = sa3 * spadiv * LOG2E;
            g_c[3] = sa4 * spadiv * LOG2E;
            g_c[4] = c1p * inv;
            g_c[5] = c2p * inv;
            g_c[6] = c3p * inv;
            g_c[7] = c4p * inv;
        }
    }
}

struct PairConsts {
    float b1, b2, b3, b4, c1n, c2n, c3n, c4n;
};

__device__ __forceinline__ void do_pair(float r, float cv, int i, int j,
                                        const float* __restrict__ s_z,
                                        const PairConsts& K,
                                        float* __restrict__ out) {
    unsigned zi = g_Z8[i];
    unsigned zj = g_Z8[j];
    float s  = s_z[zi] + s_z[zj];          // z_i + z_j
    float t  = s * r;                      // positive
    float f  = K.c1n * ex2f(-K.b1 * t)
             + K.c2n * ex2f(-K.b2 * t)
             + K.c3n * ex2f(-K.b3 * t)
             + K.c4n * ex2f(-K.b4 * t);
    float zz = (float)(zi * zj);           // exact integer product
    float contrib = (KEHALF * cv * zz) * f * frcpf(r);
    atomicAdd(out + i, contrib);           // return unused -> RED.ADD.F32
}

__global__ __launch_bounds__(256)
void pair_kernel(const float* __restrict__ rij, const float* __restrict__ cv,
                 const int* __restrict__ ii, const int* __restrict__ jj,
                 float* __restrict__ out, int P) {
    __shared__ float s_z[128];
    __shared__ float s_c[8];
    int tid = threadIdx.x;
    if (tid < 128) s_z[tid] = g_zlut[tid];
    if (tid < 8)   s_c[tid] = g_c[tid];
    __syncthreads();

    PairConsts K;
    K.b1 = s_c[0]; K.b2 = s_c[1]; K.b3 = s_c[2]; K.b4 = s_c[3];
    K.c1n = s_c[4]; K.c2n = s_c[5]; K.c3n = s_c[6]; K.c4n = s_c[7];

    long base = (long)(blockIdx.x * blockDim.x + tid) * 4;
    if (base + 4 <= (long)P) {
        float4 r4 = *(const float4*)(rij + base);
        float4 c4 = *(const float4*)(cv + base);
        int4   i4 = *(const int4*)(ii + base);
        int4   j4 = *(const int4*)(jj + base);
        do_pair(r4.x, c4.x, i4.x, j4.x, s_z, K, out);
        do_pair(r4.y, c4.y, i4.y, j4.y, s_z, K, out);
        do_pair(r4.z, c4.z, i4.z, j4.z, s_z, K, out);
        do_pair(r4.w, c4.w, i4.w, j4.w, s_z, K, out);
    } else {
        for (long p = base; p < (long)P; ++p)
            do_pair(rij[p], cv[p], ii[p], jj[p], s_z, K, out);
    }
}

extern "C" void kernel_launch(void* const* d_in, const int* in_sizes, int n_in,
                              void* d_out, int out_size) {
    const float* Zf   = (const float*)d_in[n_in - 15];
    const float* rij  = (const float*)d_in[n_in - 14];
    const float* cutv = (const float*)d_in[n_in - 13];
    const int*   ii   = (const int*)  d_in[n_in - 12];
    const int*   jj   = (const int*)  d_in[n_in - 11];
    const float* adiv = (const float*)d_in[n_in - 10];
    const float* apow = (const float*)d_in[n_in - 9];
    const float* c1   = (const float*)d_in[n_in - 8];
    const float* c2   = (const float*)d_in[n_in - 7];
    const float* c3   = (const float*)d_in[n_in - 6];
    const float* c4   = (const float*)d_in[n_in - 5];
    const float* a1   = (const float*)d_in[n_in - 4];
    const float* a2   = (const float*)d_in[n_in - 3];
    const float* a3   = (const float*)d_in[n_in - 2];
    const float* a4   = (const float*)d_in[n_in - 1];

    int natoms = in_sizes[n_in - 15];
    int P      = in_sizes[n_in - 14];
    float* out = (float*)d_out;

    // 1) per-atom prep + constants + z-LUT + output zeroing (one node)
    int pcount = (natoms > out_size) ? natoms : out_size;
    int pb = (pcount + 255) / 256;
    prep_kernel<<<pb, 256>>>(Zf, natoms, out, out_size,
                             adiv, apow, c1, c2, c3, c4, a1, a2, a3, a4);

    // 2) pair contributions, 4 pairs per thread (32 regs, occ ~90%)
    long nthreads = ((long)P + 3) / 4;
    int blocks = (int)((nthreads + 255) / 256);
    pair_kernel<<<blocks, 256>>>(rij, cutv, ii, jj, out, P);
}